// round 14
// baseline (speedup 1.0000x reference)
#include <cuda_runtime.h>
#include <cuda_fp16.h>
#include <cstdint>
#include <math.h>

#define SEQ   2048
#define DIM   512
#define KCB   8192
#define NROWS 16384
#define MARGIN  16.0f
#define RMARGIN 16.0f
#define MAXC  256

// ---------------- global scratch ----------------
__device__ __align__(16) __half g_xh[(size_t)NROWS * DIM];          // 16 MB
__device__ __align__(16) __half g_ch[(size_t)KCB * DIM];            // 8 MB
__device__ __align__(16) float g_c2[KCB];
__device__ __align__(16) float g_pe[(size_t)SEQ * DIM];             // 4 MB
__device__ int   g_cand[(size_t)NROWS * MAXC];
__device__ float g_cscore[(size_t)NROWS * MAXC];
__device__ int   g_ncand[NROWS];
__device__ float g_rowmin[NROWS];

// ---------------- helpers ----------------
__device__ __forceinline__ uint32_t smem_to_u32(const void* p) {
    uint32_t a;
    asm("{ .reg .u64 t; cvta.to.shared.u64 t, %1; cvt.u32.u64 %0, t; }" : "=r"(a) : "l"(p));
    return a;
}
__device__ __forceinline__ void ldsm4(uint32_t* r, uint32_t addr) {
    asm volatile("ldmatrix.sync.aligned.m8n8.x4.shared.b16 {%0,%1,%2,%3}, [%4];"
                 : "=r"(r[0]), "=r"(r[1]), "=r"(r[2]), "=r"(r[3]) : "r"(addr));
}
// f16 inputs, f16 accumulate
__device__ __forceinline__ void mma16816h(uint32_t* c, const uint32_t* a, uint32_t b0, uint32_t b1) {
    asm volatile("mma.sync.aligned.m16n8k16.row.col.f16.f16.f16.f16 "
                 "{%0,%1}, {%2,%3,%4,%5}, {%6,%7}, {%0,%1};"
                 : "+r"(c[0]), "+r"(c[1])
                 : "r"(a[0]), "r"(a[1]), "r"(a[2]), "r"(a[3]), "r"(b0), "r"(b1));
}
__device__ __forceinline__ unsigned fmap(float f) {
    unsigned u = __float_as_uint(f);
    return (u >> 31) ? ~u : (u | 0x80000000u);
}
__device__ __forceinline__ float funmap(unsigned m) {
    return (m >> 31) ? __uint_as_float(m & 0x7fffffffu) : __uint_as_float(~m);
}

// ---------------- screening GEMM (fp16, 3-stage cp.async ring) ----------------
// CTA: 128 rows x 8192 codes. 512 threads = 16 warps = 4 wm (m32) x 4 wn (n64).
// A resident (128 KB). B: 32 tiles of 256 codes, k64 chunks (32 KB), 3 buffers.
#define ATILE_B  131072
#define BCHUNK_B 32768
#define SMEM_DYN (ATILE_B + 3*BCHUNK_B + 1024)
#define NCHUNK   256              // 32 tiles * 8 chunks

__device__ __forceinline__ void issue_b(uint32_t dstbase, int chunk, int tid) {
    int tile = chunk >> 3, kc = chunk & 7;
    const uint4* base = (const uint4*)g_ch;
#pragma unroll
    for (int j = 0; j < 4; j++) {
        int idx = tid + j * 512;          // 0..2047 16B chunks
        int n = idx >> 3, c16 = idx & 7;  // code row 0..255, chunk 0..7 (128B rows)
        const uint4* sp = base + (size_t)(tile * 256 + n) * 64 + kc * 8 + c16;
        uint32_t d = dstbase + (uint32_t)(n * 128 + ((c16 * 16) ^ ((n & 7) << 4)));
        asm volatile("cp.async.cg.shared.global [%0], [%1], 16;" :: "r"(d), "l"(sp));
    }
}

__global__ void __launch_bounds__(512, 1) k_screen() {
    extern __shared__ char smem[];
    uint32_t sb = smem_to_u32(smem);
    uint32_t s0 = (sb + 1023) & ~1023u;
    const uint32_t A_B = s0;
    const uint32_t B_B0 = s0 + ATILE_B;
    __shared__ float c2s[256];
    __shared__ unsigned rowmin[128];

    const int tid = threadIdx.x, lane = tid & 31, warp = tid >> 5;
    const int wm = warp >> 2, wn = warp & 3;          // 4 x 4
    const int rowbase = blockIdx.x * 128;

    if (tid < 128) rowmin[tid] = 0xFFFFFFFFu;

    const uint4* ax = ((const uint4*)g_xh) + (size_t)rowbase * 64;
    for (int idx = tid; idx < 8192; idx += 512) {
        int r = idx >> 6, c16 = idx & 63;
        uint4 v = ax[idx];
        uint32_t d = A_B + (uint32_t)(r * 1024 + ((c16 * 16) ^ ((r & 7) << 4)));
        asm volatile("st.shared.v4.b32 [%0], {%1,%2,%3,%4};"
                     :: "r"(d), "r"(v.x), "r"(v.y), "r"(v.z), "r"(v.w));
    }

    const uint32_t xr  = (uint32_t)(lane & 7) << 4;
    const uint32_t aRow = A_B + (uint32_t)((wm * 32 + (lane & 7) + (lane & 8)) * 1024);
    const uint32_t akh = (uint32_t)((lane >> 4) & 1) * 16;
    const uint32_t bnoff = (uint32_t)((lane & 7) + ((lane & 16) >> 1));
    const uint32_t bkh = (uint32_t)((lane >> 3) & 1) * 16;
    const int g = lane >> 2;

    uint32_t acc[2][8][2];        // f16x2 accumulators

    // prologue: 2 chunks in flight
    issue_b(B_B0, 0, tid);
    asm volatile("cp.async.commit_group;" ::: "memory");
    issue_b(B_B0 + BCHUNK_B, 1, tid);
    asm volatile("cp.async.commit_group;" ::: "memory");

    int cur = 0;                   // (ci % 3)
    for (int ci = 0; ci < NCHUNK; ci++) {
        asm volatile("cp.async.wait_group 1;" ::: "memory");   // chunk ci landed
        __syncthreads();                                       // publish + free buf (ci+2)%3
        if (ci + 2 < NCHUNK) {
            int nxt = cur - 1; if (nxt < 0) nxt += 3;          // (ci+2) % 3
            issue_b(B_B0 + (uint32_t)(nxt * BCHUNK_B), ci + 2, tid);
            asm volatile("cp.async.commit_group;" ::: "memory");
        }

        if ((ci & 7) == 0) {
            if (tid < 256) c2s[tid] = g_c2[(ci >> 3) * 256 + tid];
#pragma unroll
            for (int a = 0; a < 2; a++)
#pragma unroll
                for (int b = 0; b < 8; b++) { acc[a][b][0] = 0u; acc[a][b][1] = 0u; }
        }

        const uint32_t kbase = (uint32_t)((ci & 7) * 128);
        const uint32_t Bb = B_B0 + (uint32_t)(cur * BCHUNK_B) + (uint32_t)(wn * 64 + bnoff) * 128;
#pragma unroll
        for (int ks = 0; ks < 4; ks++) {
            uint32_t ka = (kbase + (uint32_t)(32 * ks) + akh) ^ xr;
            uint32_t kb = ((uint32_t)(32 * ks) + bkh) ^ xr;
            uint32_t a0[4], a1[4];
            ldsm4(a0, aRow + ka);
            ldsm4(a1, aRow + 16 * 1024 + ka);
            uint32_t bv[4][4];
#pragma unroll
            for (int p = 0; p < 4; p++) ldsm4(bv[p], Bb + (uint32_t)(p * 16 * 128) + kb);
#pragma unroll
            for (int p = 0; p < 4; p++) {
                mma16816h(acc[0][2 * p],     a0, bv[p][0], bv[p][1]);
                mma16816h(acc[0][2 * p + 1], a0, bv[p][2], bv[p][3]);
                mma16816h(acc[1][2 * p],     a1, bv[p][0], bv[p][1]);
                mma16816h(acc[1][2 * p + 1], a1, bv[p][2], bv[p][3]);
            }
        }

        if ((ci & 7) == 7) {
            const int tile = ci >> 3;
#pragma unroll
            for (int ms = 0; ms < 2; ms++)
#pragma unroll
                for (int h = 0; h < 2; h++) {
                    int r = wm * 32 + ms * 16 + 8 * h + g;
                    float sc[16];
                    float mn = 3.4e38f;
#pragma unroll
                    for (int ns = 0; ns < 8; ns++) {
                        int col = wn * 64 + ns * 8 + (lane & 3) * 2;
                        float2 dd = __half22float2(*(__half2*)&acc[ms][ns][h]);
                        sc[2 * ns]     = fmaf(-2.f, dd.x, c2s[col]);
                        sc[2 * ns + 1] = fmaf(-2.f, dd.y, c2s[col + 1]);
                        mn = fminf(mn, fminf(sc[2 * ns], sc[2 * ns + 1]));
                    }
                    mn = fminf(mn, __shfl_xor_sync(0xffffffffu, mn, 1));
                    mn = fminf(mn, __shfl_xor_sync(0xffffffffu, mn, 2));
                    unsigned old = atomicMin(&rowmin[r], fmap(mn));
                    float thr = fminf(funmap(old), mn) + MARGIN;
                    int rg = rowbase + r;
#pragma unroll
                    for (int ns = 0; ns < 8; ns++) {
                        int col = wn * 64 + ns * 8 + (lane & 3) * 2;
                        if (sc[2 * ns] <= thr) {
                            int p = atomicAdd(&g_ncand[rg], 1);
                            if (p < MAXC) { g_cand[rg * MAXC + p] = tile * 256 + col; g_cscore[rg * MAXC + p] = sc[2 * ns]; }
                        }
                        if (sc[2 * ns + 1] <= thr) {
                            int p = atomicAdd(&g_ncand[rg], 1);
                            if (p < MAXC) { g_cand[rg * MAXC + p] = tile * 256 + col + 1; g_cscore[rg * MAXC + p] = sc[2 * ns + 1]; }
                        }
                    }
                }
        }
        if (++cur == 3) cur = 0;
    }
    __syncthreads();
    if (tid < 128) g_rowmin[rowbase + tid] = funmap(rowmin[tid]);
}

// ---------------- pass 2: refilter + fp32 exact rescore + gather + PE ----------------
__global__ void __launch_bounds__(256) k_select(const float* __restrict__ x,
                                                const float* __restrict__ cb,
                                                float* __restrict__ out) {
    const int r = (blockIdx.x << 3) + (threadIdx.x >> 5);
    const int lane = threadIdx.x & 31;
    const int w = threadIdx.x >> 5;
    const int nc = g_ncand[r];
    __shared__ float xs[8][DIM];
    int bk;

    if (nc <= MAXC) {
        const float thr = g_rowmin[r] + RMARGIN;
        float bestv = 3.4e38f;
        int bkk = KCB;
        const float4* xr = ((const float4*)x) + (size_t)r * 128;
        float4 xv[4];
#pragma unroll
        for (int q = 0; q < 4; q++) xv[q] = xr[lane + q * 32];
        for (int ci = 0; ci < nc; ci++) {
            if (g_cscore[r * MAXC + ci] > thr) continue;
            int k = g_cand[r * MAXC + ci];
            const float4* cr = ((const float4*)cb) + (size_t)k * 128;
            float pd = 0.f;
#pragma unroll
            for (int q = 0; q < 4; q++) {
                float4 c = cr[lane + q * 32];
                pd = fmaf(xv[q].x, c.x, pd); pd = fmaf(xv[q].y, c.y, pd);
                pd = fmaf(xv[q].z, c.z, pd); pd = fmaf(xv[q].w, c.w, pd);
            }
#pragma unroll
            for (int o = 16; o; o >>= 1) pd += __shfl_down_sync(0xffffffffu, pd, o);
            if (lane == 0) {
                float d2 = fmaf(-2.0f, pd, g_c2[k]);
                if (d2 < bestv || (d2 == bestv && k < bkk)) { bestv = d2; bkk = k; }
            }
        }
        bk = __shfl_sync(0xffffffffu, bkk, 0);
    } else {
        for (int d = lane; d < DIM; d += 32) xs[w][d] = x[(size_t)r * DIM + d];
        __syncwarp();
        const float thrfb = g_rowmin[r] + RMARGIN;
        int kl[8]; int cnt = 0;
        for (int k0 = lane; k0 < KCB; k0 += 32) {
            const uint2* crow = (const uint2*)(g_ch + (size_t)k0 * DIM);
            float dot = 0.f;
#pragma unroll 4
            for (int q = 0; q < 128; q++) {
                uint2 u = crow[q];
                float2 f0 = __half22float2(*(__half2*)&u.x);
                float2 f1 = __half22float2(*(__half2*)&u.y);
                dot += xs[w][4 * q] * f0.x + xs[w][4 * q + 1] * f0.y
                     + xs[w][4 * q + 2] * f1.x + xs[w][4 * q + 3] * f1.y;
            }
            float s = fmaf(-2.f, dot, g_c2[k0]);
            if (s <= thrfb && cnt < 8) kl[cnt++] = k0;
        }
        float bv = 3.4e38f; int bkk = KCB;
        for (int c = 0; c < cnt; c++) {
            int k = kl[c];
            const float* cr = cb + (size_t)k * DIM;
            float pd = 0.f;
            for (int d = 0; d < DIM; d++) pd = fmaf(xs[w][d], cr[d], pd);
            float d2 = fmaf(-2.0f, pd, g_c2[k]);
            if (d2 < bv || (d2 == bv && k < bkk)) { bv = d2; bkk = k; }
        }
        for (int o = 16; o; o >>= 1) {
            float ov = __shfl_down_sync(0xffffffffu, bv, o);
            int ok = __shfl_down_sync(0xffffffffu, bkk, o);
            if (ov < bv || (ov == bv && ok < bkk)) { bv = ov; bkk = ok; }
        }
        bk = __shfl_sync(0xffffffffu, bkk, 0);
    }

    const int s = r & (SEQ - 1);
    const float4* cr = ((const float4*)cb) + (size_t)bk * 128;
    const float4* pr = ((const float4*)g_pe) + (size_t)s * 128;
    float4* o4 = ((float4*)out) + (size_t)r * 128;
#pragma unroll
    for (int q = 0; q < 4; q++) {
        float4 c = cr[lane + q * 32], p = pr[lane + q * 32];
        o4[lane + q * 32] = make_float4(c.x + p.x, c.y + p.y, c.z + p.z, c.w + p.w);
    }
}

// ---------------- prep kernels ----------------
__global__ void k_prep_x(const float4* __restrict__ x) {
    int i = blockIdx.x * blockDim.x + threadIdx.x;
    if (i < NROWS * DIM / 4) {
        float4 v = x[i];
        __half2 a = __floats2half2_rn(v.x, v.y);
        __half2 b = __floats2half2_rn(v.z, v.w);
        reinterpret_cast<uint2*>(g_xh)[i] =
            make_uint2(*reinterpret_cast<uint32_t*>(&a), *reinterpret_cast<uint32_t*>(&b));
    }
    if (i < NROWS) g_ncand[i] = 0;
}

__global__ void k_prep_cb(const float* __restrict__ cb) {
    int row = blockIdx.x, tid = threadIdx.x;
    float p = 0.0f;
    for (int d = tid; d < DIM; d += 128) {
        float v = cb[(size_t)row * DIM + d];
        g_ch[(size_t)row * DIM + d] = __float2half_rn(v);
        p = fmaf(v, v, p);
    }
#pragma unroll
    for (int off = 16; off; off >>= 1) p += __shfl_down_sync(0xffffffffu, p, off);
    __shared__ float r4[4];
    if ((tid & 31) == 0) r4[tid >> 5] = p;
    __syncthreads();
    if (tid == 0) g_c2[row] = r4[0] + r4[1] + r4[2] + r4[3];
}

__global__ void k_prep_pe() {
    int s = blockIdx.x;
    int i = threadIdx.x;
    const float c = (float)(9.210340371976184 / 512.0);
    float dvf = expf(-(float)(2 * i) * c);
    float angf = (float)s * dvf;
    float n = rintf(angf * 0.15915494309189535f);
    float rf = (float)((double)angf - (double)n * 6.283185307179586477);
    g_pe[(size_t)s * DIM + 2 * i]     = sinf(rf);
    g_pe[(size_t)s * DIM + 2 * i + 1] = cosf(rf);
}

// ---------------- launch ----------------
extern "C" void kernel_launch(void* const* d_in, const int* in_sizes, int n_in,
                              void* d_out, int out_size) {
    const float* x  = (const float*)d_in[0];
    const float* cb = (const float*)d_in[1];
    float* out = (float*)d_out;

    cudaFuncSetAttribute(k_screen, cudaFuncAttributeMaxDynamicSharedMemorySize, SMEM_DYN);

    k_prep_x<<<(NROWS * DIM / 4 + 255) / 256, 256>>>((const float4*)x);
    k_prep_cb<<<KCB, 128>>>(cb);
    k_prep_pe<<<SEQ, 256>>>();
    k_screen<<<128, 512, SMEM_DYN>>>();
    k_select<<<NROWS / 8, 256>>>(x, cb, out);
}

// round 15
// speedup vs baseline: 1.0084x; 1.0084x over previous
#include <cuda_runtime.h>
#include <cuda_fp16.h>
#include <cstdint>
#include <math.h>

#define SEQ   2048
#define DIM   512
#define KCB   8192
#define NROWS 16384
#define MARGIN  16.0f
#define RMARGIN 16.0f
#define MAXC  256

// ---------------- global scratch ----------------
__device__ __align__(16) __half g_xh[(size_t)NROWS * DIM];          // 16 MB
__device__ __align__(16) __half g_ch[(size_t)KCB * DIM];            // 8 MB
__device__ __align__(16) float g_c2[KCB];
__device__ __align__(16) float g_pe[(size_t)SEQ * DIM];             // 4 MB
__device__ int   g_cand[(size_t)NROWS * MAXC];
__device__ float g_cscore[(size_t)NROWS * MAXC];
__device__ int   g_ncand[NROWS];
__device__ float g_rowmin[NROWS];

// ---------------- helpers ----------------
__device__ __forceinline__ uint32_t smem_to_u32(const void* p) {
    uint32_t a;
    asm("{ .reg .u64 t; cvta.to.shared.u64 t, %1; cvt.u32.u64 %0, t; }" : "=r"(a) : "l"(p));
    return a;
}
__device__ __forceinline__ void ldsm4(uint32_t* r, uint32_t addr) {
    asm volatile("ldmatrix.sync.aligned.m8n8.x4.shared.b16 {%0,%1,%2,%3}, [%4];"
                 : "=r"(r[0]), "=r"(r[1]), "=r"(r[2]), "=r"(r[3]) : "r"(addr));
}
// f16 inputs, f16 accumulate
__device__ __forceinline__ void mma16816h(uint32_t* c, const uint32_t* a, uint32_t b0, uint32_t b1) {
    asm volatile("mma.sync.aligned.m16n8k16.row.col.f16.f16.f16.f16 "
                 "{%0,%1}, {%2,%3,%4,%5}, {%6,%7}, {%0,%1};"
                 : "+r"(c[0]), "+r"(c[1])
                 : "r"(a[0]), "r"(a[1]), "r"(a[2]), "r"(a[3]), "r"(b0), "r"(b1));
}
__device__ __forceinline__ unsigned fmap(float f) {
    unsigned u = __float_as_uint(f);
    return (u >> 31) ? ~u : (u | 0x80000000u);
}
__device__ __forceinline__ float funmap(unsigned m) {
    return (m >> 31) ? __uint_as_float(m & 0x7fffffffu) : __uint_as_float(~m);
}

// ---------------- screening GEMM (fp16, 3-stage ring, ks-pipelined frags) ----------------
// CTA: 128 rows x 8192 codes. 512 threads = 16 warps = 4 wm (m32) x 4 wn (n64).
#define ATILE_B  131072
#define BCHUNK_B 32768
#define SMEM_DYN (ATILE_B + 3*BCHUNK_B + 1024)
#define NCHUNK   256              // 32 tiles * 8 chunks

__device__ __forceinline__ void issue_b(uint32_t dstbase, int chunk, int tid) {
    int tile = chunk >> 3, kc = chunk & 7;
    const uint4* base = (const uint4*)g_ch;
#pragma unroll
    for (int j = 0; j < 4; j++) {
        int idx = tid + j * 512;
        int n = idx >> 3, c16 = idx & 7;
        const uint4* sp = base + (size_t)(tile * 256 + n) * 64 + kc * 8 + c16;
        uint32_t d = dstbase + (uint32_t)(n * 128 + ((c16 * 16) ^ ((n & 7) << 4)));
        asm volatile("cp.async.cg.shared.global [%0], [%1], 16;" :: "r"(d), "l"(sp));
    }
}

__global__ void __launch_bounds__(512, 1) k_screen() {
    extern __shared__ char smem[];
    uint32_t sb = smem_to_u32(smem);
    uint32_t s0 = (sb + 1023) & ~1023u;
    const uint32_t A_B = s0;
    const uint32_t B_B0 = s0 + ATILE_B;
    __shared__ float c2s[256];
    __shared__ unsigned rowmin[128];

    const int tid = threadIdx.x, lane = tid & 31, warp = tid >> 5;
    const int wm = warp >> 2, wn = warp & 3;          // 4 x 4
    const int rowbase = blockIdx.x * 128;

    if (tid < 128) rowmin[tid] = 0xFFFFFFFFu;

    const uint4* ax = ((const uint4*)g_xh) + (size_t)rowbase * 64;
    for (int idx = tid; idx < 8192; idx += 512) {
        int r = idx >> 6, c16 = idx & 63;
        uint4 v = ax[idx];
        uint32_t d = A_B + (uint32_t)(r * 1024 + ((c16 * 16) ^ ((r & 7) << 4)));
        asm volatile("st.shared.v4.b32 [%0], {%1,%2,%3,%4};"
                     :: "r"(d), "r"(v.x), "r"(v.y), "r"(v.z), "r"(v.w));
    }

    const uint32_t xr  = (uint32_t)(lane & 7) << 4;
    const uint32_t aRow = A_B + (uint32_t)((wm * 32 + (lane & 7) + (lane & 8)) * 1024);
    const uint32_t akh = (uint32_t)((lane >> 4) & 1) * 16;
    const uint32_t bnoff = (uint32_t)((lane & 7) + ((lane & 16) >> 1));
    const uint32_t bkh = (uint32_t)((lane >> 3) & 1) * 16;
    const int g = lane >> 2;

    uint32_t acc[2][8][2];        // f16x2 accumulators

    // prologue: 2 chunks in flight
    issue_b(B_B0, 0, tid);
    asm volatile("cp.async.commit_group;" ::: "memory");
    issue_b(B_B0 + BCHUNK_B, 1, tid);
    asm volatile("cp.async.commit_group;" ::: "memory");

    int cur = 0;                   // ci % 3
    for (int ci = 0; ci < NCHUNK; ci++) {
        asm volatile("cp.async.wait_group 1;" ::: "memory");
        __syncthreads();
        if (ci + 2 < NCHUNK) {
            int nxt = cur - 1; if (nxt < 0) nxt += 3;
            issue_b(B_B0 + (uint32_t)(nxt * BCHUNK_B), ci + 2, tid);
            asm volatile("cp.async.commit_group;" ::: "memory");
        }

        if ((ci & 7) == 0) {
            if (tid < 256) c2s[tid] = g_c2[(ci >> 3) * 256 + tid];
#pragma unroll
            for (int a = 0; a < 2; a++)
#pragma unroll
                for (int b = 0; b < 8; b++) { acc[a][b][0] = 0u; acc[a][b][1] = 0u; }
        }

        const uint32_t kbase = (uint32_t)((ci & 7) * 128);
        const uint32_t Bb = B_B0 + (uint32_t)(cur * BCHUNK_B) + (uint32_t)(wn * 64 + bnoff) * 128;

        // ks-level fragment double-buffer: load ks+1 before computing ks
        uint32_t af[2][2][4], bf[2][4][4];
#define LOADF(st, ks) do { \
        uint32_t ka = (kbase + (uint32_t)(32 * (ks)) + akh) ^ xr; \
        uint32_t kb = ((uint32_t)(32 * (ks)) + bkh) ^ xr; \
        ldsm4(af[st][0], aRow + ka); \
        ldsm4(af[st][1], aRow + 16 * 1024 + ka); \
        _Pragma("unroll") \
        for (int p = 0; p < 4; p++) ldsm4(bf[st][p], Bb + (uint32_t)(p * 16 * 128) + kb); \
    } while (0)

        LOADF(0, 0);
#pragma unroll
        for (int ks = 0; ks < 4; ks++) {
            const int c = ks & 1;
            if (ks < 3) LOADF(c ^ 1, ks + 1);
#pragma unroll
            for (int p = 0; p < 4; p++) {
                mma16816h(acc[0][2 * p],     af[c][0], bf[c][p][0], bf[c][p][1]);
                mma16816h(acc[0][2 * p + 1], af[c][0], bf[c][p][2], bf[c][p][3]);
                mma16816h(acc[1][2 * p],     af[c][1], bf[c][p][0], bf[c][p][1]);
                mma16816h(acc[1][2 * p + 1], af[c][1], bf[c][p][2], bf[c][p][3]);
            }
        }
#undef LOADF

        if ((ci & 7) == 7) {
            const int tile = ci >> 3;
#pragma unroll
            for (int ms = 0; ms < 2; ms++)
#pragma unroll
                for (int h = 0; h < 2; h++) {
                    int r = wm * 32 + ms * 16 + 8 * h + g;
                    float sc[16];
                    float mn = 3.4e38f;
#pragma unroll
                    for (int ns = 0; ns < 8; ns++) {
                        int col = wn * 64 + ns * 8 + (lane & 3) * 2;
                        float2 dd = __half22float2(*(__half2*)&acc[ms][ns][h]);
                        sc[2 * ns]     = fmaf(-2.f, dd.x, c2s[col]);
                        sc[2 * ns + 1] = fmaf(-2.f, dd.y, c2s[col + 1]);
                        mn = fminf(mn, fminf(sc[2 * ns], sc[2 * ns + 1]));
                    }
                    mn = fminf(mn, __shfl_xor_sync(0xffffffffu, mn, 1));
                    mn = fminf(mn, __shfl_xor_sync(0xffffffffu, mn, 2));
                    unsigned old = atomicMin(&rowmin[r], fmap(mn));
                    float thr = fminf(funmap(old), mn) + MARGIN;
                    int rg = rowbase + r;
#pragma unroll
                    for (int ns = 0; ns < 8; ns++) {
                        int col = wn * 64 + ns * 8 + (lane & 3) * 2;
                        if (sc[2 * ns] <= thr) {
                            int p = atomicAdd(&g_ncand[rg], 1);
                            if (p < MAXC) { g_cand[rg * MAXC + p] = tile * 256 + col; g_cscore[rg * MAXC + p] = sc[2 * ns]; }
                        }
                        if (sc[2 * ns + 1] <= thr) {
                            int p = atomicAdd(&g_ncand[rg], 1);
                            if (p < MAXC) { g_cand[rg * MAXC + p] = tile * 256 + col + 1; g_cscore[rg * MAXC + p] = sc[2 * ns + 1]; }
                        }
                    }
                }
        }
        if (++cur == 3) cur = 0;
    }
    __syncthreads();
    if (tid < 128) g_rowmin[rowbase + tid] = funmap(rowmin[tid]);
}

// ---------------- pass 2: refilter + fp32 exact rescore + gather + PE ----------------
__global__ void __launch_bounds__(256) k_select(const float* __restrict__ x,
                                                const float* __restrict__ cb,
                                                float* __restrict__ out) {
    const int r = (blockIdx.x << 3) + (threadIdx.x >> 5);
    const int lane = threadIdx.x & 31;
    const int w = threadIdx.x >> 5;
    const int nc = g_ncand[r];
    __shared__ float xs[8][DIM];
    int bk;

    if (nc <= MAXC) {
        const float thr = g_rowmin[r] + RMARGIN;
        float bestv = 3.4e38f;
        int bkk = KCB;
        const float4* xr = ((const float4*)x) + (size_t)r * 128;
        float4 xv[4];
#pragma unroll
        for (int q = 0; q < 4; q++) xv[q] = xr[lane + q * 32];
        for (int ci = 0; ci < nc; ci++) {
            if (g_cscore[r * MAXC + ci] > thr) continue;
            int k = g_cand[r * MAXC + ci];
            const float4* cr = ((const float4*)cb) + (size_t)k * 128;
            float pd = 0.f;
#pragma unroll
            for (int q = 0; q < 4; q++) {
                float4 c = cr[lane + q * 32];
                pd = fmaf(xv[q].x, c.x, pd); pd = fmaf(xv[q].y, c.y, pd);
                pd = fmaf(xv[q].z, c.z, pd); pd = fmaf(xv[q].w, c.w, pd);
            }
#pragma unroll
            for (int o = 16; o; o >>= 1) pd += __shfl_down_sync(0xffffffffu, pd, o);
            if (lane == 0) {
                float d2 = fmaf(-2.0f, pd, g_c2[k]);
                if (d2 < bestv || (d2 == bestv && k < bkk)) { bestv = d2; bkk = k; }
            }
        }
        bk = __shfl_sync(0xffffffffu, bkk, 0);
    } else {
        for (int d = lane; d < DIM; d += 32) xs[w][d] = x[(size_t)r * DIM + d];
        __syncwarp();
        const float thrfb = g_rowmin[r] + RMARGIN;
        int kl[8]; int cnt = 0;
        for (int k0 = lane; k0 < KCB; k0 += 32) {
            const uint2* crow = (const uint2*)(g_ch + (size_t)k0 * DIM);
            float dot = 0.f;
#pragma unroll 4
            for (int q = 0; q < 128; q++) {
                uint2 u = crow[q];
                float2 f0 = __half22float2(*(__half2*)&u.x);
                float2 f1 = __half22float2(*(__half2*)&u.y);
                dot += xs[w][4 * q] * f0.x + xs[w][4 * q + 1] * f0.y
                     + xs[w][4 * q + 2] * f1.x + xs[w][4 * q + 3] * f1.y;
            }
            float s = fmaf(-2.f, dot, g_c2[k0]);
            if (s <= thrfb && cnt < 8) kl[cnt++] = k0;
        }
        float bv = 3.4e38f; int bkk = KCB;
        for (int c = 0; c < cnt; c++) {
            int k = kl[c];
            const float* cr = cb + (size_t)k * DIM;
            float pd = 0.f;
            for (int d = 0; d < DIM; d++) pd = fmaf(xs[w][d], cr[d], pd);
            float d2 = fmaf(-2.0f, pd, g_c2[k]);
            if (d2 < bv || (d2 == bv && k < bkk)) { bv = d2; bkk = k; }
        }
        for (int o = 16; o; o >>= 1) {
            float ov = __shfl_down_sync(0xffffffffu, bv, o);
            int ok = __shfl_down_sync(0xffffffffu, bkk, o);
            if (ov < bv || (ov == bv && ok < bkk)) { bv = ov; bkk = ok; }
        }
        bk = __shfl_sync(0xffffffffu, bkk, 0);
    }

    const int s = r & (SEQ - 1);
    const float4* cr = ((const float4*)cb) + (size_t)bk * 128;
    const float4* pr = ((const float4*)g_pe) + (size_t)s * 128;
    float4* o4 = ((float4*)out) + (size_t)r * 128;
#pragma unroll
    for (int q = 0; q < 4; q++) {
        float4 c = cr[lane + q * 32], p = pr[lane + q * 32];
        o4[lane + q * 32] = make_float4(c.x + p.x, c.y + p.y, c.z + p.z, c.w + p.w);
    }
}

// ---------------- prep kernels ----------------
__global__ void k_prep_x(const float4* __restrict__ x) {
    int i = blockIdx.x * blockDim.x + threadIdx.x;
    if (i < NROWS * DIM / 4) {
        float4 v = x[i];
        __half2 a = __floats2half2_rn(v.x, v.y);
        __half2 b = __floats2half2_rn(v.z, v.w);
        reinterpret_cast<uint2*>(g_xh)[i] =
            make_uint2(*reinterpret_cast<uint32_t*>(&a), *reinterpret_cast<uint32_t*>(&b));
    }
    if (i < NROWS) g_ncand[i] = 0;
}

__global__ void k_prep_cb(const float* __restrict__ cb) {
    int row = blockIdx.x, tid = threadIdx.x;
    float p = 0.0f;
    for (int d = tid; d < DIM; d += 128) {
        float v = cb[(size_t)row * DIM + d];
        g_ch[(size_t)row * DIM + d] = __float2half_rn(v);
        p = fmaf(v, v, p);
    }
#pragma unroll
    for (int off = 16; off; off >>= 1) p += __shfl_down_sync(0xffffffffu, p, off);
    __shared__ float r4[4];
    if ((tid & 31) == 0) r4[tid >> 5] = p;
    __syncthreads();
    if (tid == 0) g_c2[row] = r4[0] + r4[1] + r4[2] + r4[3];
}

__global__ void k_prep_pe() {
    int s = blockIdx.x;
    int i = threadIdx.x;
    const float c = (float)(9.210340371976184 / 512.0);
    float dvf = expf(-(float)(2 * i) * c);
    float angf = (float)s * dvf;
    float n = rintf(angf * 0.15915494309189535f);
    float rf = (float)((double)angf - (double)n * 6.283185307179586477);
    g_pe[(size_t)s * DIM + 2 * i]     = sinf(rf);
    g_pe[(size_t)s * DIM + 2 * i + 1] = cosf(rf);
}

// ---------------- launch ----------------
extern "C" void kernel_launch(void* const* d_in, const int* in_sizes, int n_in,
                              void* d_out, int out_size) {
    const float* x  = (const float*)d_in[0];
    const float* cb = (const float*)d_in[1];
    float* out = (float*)d_out;

    cudaFuncSetAttribute(k_screen, cudaFuncAttributeMaxDynamicSharedMemorySize, SMEM_DYN);

    k_prep_x<<<(NROWS * DIM / 4 + 255) / 256, 256>>>((const float4*)x);
    k_prep_cb<<<KCB, 128>>>(cb);
    k_prep_pe<<<SEQ, 256>>>();
    k_screen<<<128, 512, SMEM_DYN>>>();
    k_select<<<NROWS / 8, 256>>>(x, cb, out);
}

// round 16
// speedup vs baseline: 1.0308x; 1.0222x over previous
#include <cuda_runtime.h>
#include <cuda_fp16.h>
#include <cstdint>
#include <math.h>

#define SEQ   2048
#define DIM   512
#define KCB   8192
#define NROWS 16384
#define MARGIN  16.0f
#define RMARGIN 16.0f
#define MAXC  256
#define GRIDN 148
#define NITEM 4096               // 128 rowtiles * 32 code-tiles

// ---------------- global scratch ----------------
__device__ __align__(16) __half g_xh[(size_t)NROWS * DIM];          // 16 MB
__device__ __align__(16) __half g_ch[(size_t)KCB * DIM];            // 8 MB
__device__ __align__(16) float g_c2[KCB];
__device__ __align__(16) float g_pe[(size_t)SEQ * DIM];             // 4 MB
__device__ int      g_cand[(size_t)NROWS * MAXC];
__device__ float    g_cscore[(size_t)NROWS * MAXC];
__device__ int      g_ncand[NROWS];
__device__ unsigned g_rowminu[NROWS];

// ---------------- helpers ----------------
__device__ __forceinline__ uint32_t smem_to_u32(const void* p) {
    uint32_t a;
    asm("{ .reg .u64 t; cvta.to.shared.u64 t, %1; cvt.u32.u64 %0, t; }" : "=r"(a) : "l"(p));
    return a;
}
__device__ __forceinline__ void ldsm4(uint32_t* r, uint32_t addr) {
    asm volatile("ldmatrix.sync.aligned.m8n8.x4.shared.b16 {%0,%1,%2,%3}, [%4];"
                 : "=r"(r[0]), "=r"(r[1]), "=r"(r[2]), "=r"(r[3]) : "r"(addr));
}
__device__ __forceinline__ void mma16816h(uint32_t* c, const uint32_t* a, uint32_t b0, uint32_t b1) {
    asm volatile("mma.sync.aligned.m16n8k16.row.col.f16.f16.f16.f16 "
                 "{%0,%1}, {%2,%3,%4,%5}, {%6,%7}, {%0,%1};"
                 : "+r"(c[0]), "+r"(c[1])
                 : "r"(a[0]), "r"(a[1]), "r"(a[2]), "r"(a[3]), "r"(b0), "r"(b1));
}
__device__ __forceinline__ unsigned fmap(float f) {
    unsigned u = __float_as_uint(f);
    return (u >> 31) ? ~u : (u | 0x80000000u);
}
__device__ __forceinline__ float funmap(unsigned m) {
    return (m >> 31) ? __uint_as_float(m & 0x7fffffffu) : __uint_as_float(~m);
}

// ---------------- screening GEMM (fp16, flattened 148-CTA grid) ----------------
#define ATILE_B  131072
#define BCHUNK_B 32768
#define SMEM_DYN (ATILE_B + 3*BCHUNK_B + 1024)

__device__ __forceinline__ void issue_b(uint32_t dstbase, int tile, int kc, int tid) {
    const uint4* base = (const uint4*)g_ch;
#pragma unroll
    for (int j = 0; j < 4; j++) {
        int idx = tid + j * 512;
        int n = idx >> 3, c16 = idx & 7;
        const uint4* sp = base + (size_t)(tile * 256 + n) * 64 + kc * 8 + c16;
        uint32_t d = dstbase + (uint32_t)(n * 128 + ((c16 * 16) ^ ((n & 7) << 4)));
        asm volatile("cp.async.cg.shared.global [%0], [%1], 16;" :: "r"(d), "l"(sp));
    }
}

__global__ void __launch_bounds__(512, 1) k_screen() {
    extern __shared__ char smem[];
    uint32_t sb = smem_to_u32(smem);
    uint32_t s0 = (sb + 1023) & ~1023u;
    const uint32_t A_B = s0;
    const uint32_t B_B0 = s0 + ATILE_B;
    __shared__ float c2s[256];
    __shared__ unsigned rowmin[128];

    const int tid = threadIdx.x, lane = tid & 31, warp = tid >> 5;
    const int wm = warp >> 2, wn = warp & 3;          // 4 x 4
    const int bid = blockIdx.x;

    const int w0 = (int)(((long long)bid * NITEM) / GRIDN);
    const int w1 = (int)(((long long)(bid + 1) * NITEM) / GRIDN);
    const int NCH = (w1 - w0) * 8;

    if (tid < 128) rowmin[tid] = 0xFFFFFFFFu;
    int currow = -1;

    const uint32_t xr  = (uint32_t)(lane & 7) << 4;
    const uint32_t aRow = A_B + (uint32_t)((wm * 32 + (lane & 7) + (lane & 8)) * 1024);
    const uint32_t akh = (uint32_t)((lane >> 4) & 1) * 16;
    const uint32_t bnoff = (uint32_t)((lane & 7) + ((lane & 16) >> 1));
    const uint32_t bkh = (uint32_t)((lane >> 3) & 1) * 16;
    const int g = lane >> 2;

    uint32_t acc[2][8][2];

    // prologue: 2 chunks in flight (both belong to item w0)
    issue_b(B_B0, w0 & 31, 0, tid);
    asm volatile("cp.async.commit_group;" ::: "memory");
    issue_b(B_B0 + BCHUNK_B, w0 & 31, 1, tid);
    asm volatile("cp.async.commit_group;" ::: "memory");

    int cur = 0;                   // ci % 3
    for (int ci = 0; ci < NCH; ci++) {
        if (ci + 2 < NCH) asm volatile("cp.async.wait_group 1;" ::: "memory");
        else              asm volatile("cp.async.wait_group 0;" ::: "memory");
        __syncthreads();
        if (ci + 2 < NCH) {
            int nxt = cur - 1; if (nxt < 0) nxt += 3;
            int it2 = w0 + ((ci + 2) >> 3);
            issue_b(B_B0 + (uint32_t)(nxt * BCHUNK_B), it2 & 31, (ci + 2) & 7, tid);
            asm volatile("cp.async.commit_group;" ::: "memory");
        }

        const int item = w0 + (ci >> 3);
        const int tile = item & 31;

        if ((ci & 7) == 0) {
            const int rowtile = item >> 5;
            if (rowtile != currow) {
                if (currow >= 0 && tid < 128) {
                    atomicMin(&g_rowminu[currow * 128 + tid], rowmin[tid]);
                    rowmin[tid] = 0xFFFFFFFFu;
                }
                // load A for this rowtile (old readers ordered by chunk-top sync)
                const uint4* ax = ((const uint4*)g_xh) + (size_t)rowtile * 128 * 64;
                for (int idx = tid; idx < 8192; idx += 512) {
                    int r = idx >> 6, c16 = idx & 63;
                    uint4 v = ax[idx];
                    uint32_t d = A_B + (uint32_t)(r * 1024 + ((c16 * 16) ^ ((r & 7) << 4)));
                    asm volatile("st.shared.v4.b32 [%0], {%1,%2,%3,%4};"
                                 :: "r"(d), "r"(v.x), "r"(v.y), "r"(v.z), "r"(v.w));
                }
                __syncthreads();
                currow = rowtile;
            }
            if (tid < 256) c2s[tid] = g_c2[tile * 256 + tid];
#pragma unroll
            for (int a = 0; a < 2; a++)
#pragma unroll
                for (int b = 0; b < 8; b++) { acc[a][b][0] = 0u; acc[a][b][1] = 0u; }
        }

        const uint32_t kbase = (uint32_t)((ci & 7) * 128);
        const uint32_t Bb = B_B0 + (uint32_t)(cur * BCHUNK_B) + (uint32_t)(wn * 64 + bnoff) * 128;

        uint32_t af[2][2][4], bf[2][4][4];
#define LOADF(st, ks) do { \
        uint32_t ka = (kbase + (uint32_t)(32 * (ks)) + akh) ^ xr; \
        uint32_t kb = ((uint32_t)(32 * (ks)) + bkh) ^ xr; \
        ldsm4(af[st][0], aRow + ka); \
        ldsm4(af[st][1], aRow + 16 * 1024 + ka); \
        _Pragma("unroll") \
        for (int p = 0; p < 4; p++) ldsm4(bf[st][p], Bb + (uint32_t)(p * 16 * 128) + kb); \
    } while (0)

        LOADF(0, 0);
#pragma unroll
        for (int ks = 0; ks < 4; ks++) {
            const int c = ks & 1;
            if (ks < 3) LOADF(c ^ 1, ks + 1);
#pragma unroll
            for (int p = 0; p < 4; p++) {
                mma16816h(acc[0][2 * p],     af[c][0], bf[c][p][0], bf[c][p][1]);
                mma16816h(acc[0][2 * p + 1], af[c][0], bf[c][p][2], bf[c][p][3]);
                mma16816h(acc[1][2 * p],     af[c][1], bf[c][p][0], bf[c][p][1]);
                mma16816h(acc[1][2 * p + 1], af[c][1], bf[c][p][2], bf[c][p][3]);
            }
        }
#undef LOADF

        if ((ci & 7) == 7) {
#pragma unroll
            for (int ms = 0; ms < 2; ms++)
#pragma unroll
                for (int h = 0; h < 2; h++) {
                    int r = wm * 32 + ms * 16 + 8 * h + g;
                    float sc[16];
                    float mn = 3.4e38f;
#pragma unroll
                    for (int ns = 0; ns < 8; ns++) {
                        int col = wn * 64 + ns * 8 + (lane & 3) * 2;
                        float2 dd = __half22float2(*(__half2*)&acc[ms][ns][h]);
                        sc[2 * ns]     = fmaf(-2.f, dd.x, c2s[col]);
                        sc[2 * ns + 1] = fmaf(-2.f, dd.y, c2s[col + 1]);
                        mn = fminf(mn, fminf(sc[2 * ns], sc[2 * ns + 1]));
                    }
                    mn = fminf(mn, __shfl_xor_sync(0xffffffffu, mn, 1));
                    mn = fminf(mn, __shfl_xor_sync(0xffffffffu, mn, 2));
                    unsigned old = atomicMin(&rowmin[r], fmap(mn));
                    float thr = fminf(funmap(old), mn) + MARGIN;
                    int rg = currow * 128 + r;
#pragma unroll
                    for (int ns = 0; ns < 8; ns++) {
                        int col = wn * 64 + ns * 8 + (lane & 3) * 2;
                        if (sc[2 * ns] <= thr) {
                            int p = atomicAdd(&g_ncand[rg], 1);
                            if (p < MAXC) { g_cand[rg * MAXC + p] = tile * 256 + col; g_cscore[rg * MAXC + p] = sc[2 * ns]; }
                        }
                        if (sc[2 * ns + 1] <= thr) {
                            int p = atomicAdd(&g_ncand[rg], 1);
                            if (p < MAXC) { g_cand[rg * MAXC + p] = tile * 256 + col + 1; g_cscore[rg * MAXC + p] = sc[2 * ns + 1]; }
                        }
                    }
                }
        }
        if (++cur == 3) cur = 0;
    }
    __syncthreads();
    if (currow >= 0 && tid < 128)
        atomicMin(&g_rowminu[currow * 128 + tid], rowmin[tid]);
}

// ---------------- pass 2: refilter + fp32 exact rescore + gather + PE ----------------
__global__ void __launch_bounds__(256) k_select(const float* __restrict__ x,
                                                const float* __restrict__ cb,
                                                float* __restrict__ out) {
    const int r = (blockIdx.x << 3) + (threadIdx.x >> 5);
    const int lane = threadIdx.x & 31;
    const int w = threadIdx.x >> 5;
    const int nc = g_ncand[r];
    const float rmn = funmap(g_rowminu[r]);
    __shared__ float xs[8][DIM];
    int bk;

    if (nc <= MAXC) {
        const float thr = rmn + RMARGIN;
        float bestv = 3.4e38f;
        int bkk = KCB;
        const float4* xr = ((const float4*)x) + (size_t)r * 128;
        float4 xv[4];
#pragma unroll
        for (int q = 0; q < 4; q++) xv[q] = xr[lane + q * 32];
        for (int ci = 0; ci < nc; ci++) {
            if (g_cscore[r * MAXC + ci] > thr) continue;
            int k = g_cand[r * MAXC + ci];
            const float4* cr = ((const float4*)cb) + (size_t)k * 128;
            float pd = 0.f;
#pragma unroll
            for (int q = 0; q < 4; q++) {
                float4 c = cr[lane + q * 32];
                pd = fmaf(xv[q].x, c.x, pd); pd = fmaf(xv[q].y, c.y, pd);
                pd = fmaf(xv[q].z, c.z, pd); pd = fmaf(xv[q].w, c.w, pd);
            }
#pragma unroll
            for (int o = 16; o; o >>= 1) pd += __shfl_down_sync(0xffffffffu, pd, o);
            if (lane == 0) {
                float d2 = fmaf(-2.0f, pd, g_c2[k]);
                if (d2 < bestv || (d2 == bestv && k < bkk)) { bestv = d2; bkk = k; }
            }
        }
        bk = __shfl_sync(0xffffffffu, bkk, 0);
    } else {
        for (int d = lane; d < DIM; d += 32) xs[w][d] = x[(size_t)r * DIM + d];
        __syncwarp();
        const float thrfb = rmn + RMARGIN;
        int kl[8]; int cnt = 0;
        for (int k0 = lane; k0 < KCB; k0 += 32) {
            const uint2* crow = (const uint2*)(g_ch + (size_t)k0 * DIM);
            float dot = 0.f;
#pragma unroll 4
            for (int q = 0; q < 128; q++) {
                uint2 u = crow[q];
                float2 f0 = __half22float2(*(__half2*)&u.x);
                float2 f1 = __half22float2(*(__half2*)&u.y);
                dot += xs[w][4 * q] * f0.x + xs[w][4 * q + 1] * f0.y
                     + xs[w][4 * q + 2] * f1.x + xs[w][4 * q + 3] * f1.y;
            }
            float s = fmaf(-2.f, dot, g_c2[k0]);
            if (s <= thrfb && cnt < 8) kl[cnt++] = k0;
        }
        float bv = 3.4e38f; int bkk = KCB;
        for (int c = 0; c < cnt; c++) {
            int k = kl[c];
            const float* cr = cb + (size_t)k * DIM;
            float pd = 0.f;
            for (int d = 0; d < DIM; d++) pd = fmaf(xs[w][d], cr[d], pd);
            float d2 = fmaf(-2.0f, pd, g_c2[k]);
            if (d2 < bv || (d2 == bv && k < bkk)) { bv = d2; bkk = k; }
        }
        for (int o = 16; o; o >>= 1) {
            float ov = __shfl_down_sync(0xffffffffu, bv, o);
            int ok = __shfl_down_sync(0xffffffffu, bkk, o);
            if (ov < bv || (ov == bv && ok < bkk)) { bv = ov; bkk = ok; }
        }
        bk = __shfl_sync(0xffffffffu, bkk, 0);
    }

    const int s = r & (SEQ - 1);
    const float4* cr = ((const float4*)cb) + (size_t)bk * 128;
    const float4* pr = ((const float4*)g_pe) + (size_t)s * 128;
    float4* o4 = ((float4*)out) + (size_t)r * 128;
#pragma unroll
    for (int q = 0; q < 4; q++) {
        float4 c = cr[lane + q * 32], p = pr[lane + q * 32];
        o4[lane + q * 32] = make_float4(c.x + p.x, c.y + p.y, c.z + p.z, c.w + p.w);
    }
}

// ---------------- prep kernels ----------------
__global__ void k_prep_x(const float4* __restrict__ x) {
    int i = blockIdx.x * blockDim.x + threadIdx.x;
    if (i < NROWS * DIM / 4) {
        float4 v = x[i];
        __half2 a = __floats2half2_rn(v.x, v.y);
        __half2 b = __floats2half2_rn(v.z, v.w);
        reinterpret_cast<uint2*>(g_xh)[i] =
            make_uint2(*reinterpret_cast<uint32_t*>(&a), *reinterpret_cast<uint32_t*>(&b));
    }
    if (i < NROWS) { g_ncand[i] = 0; g_rowminu[i] = 0xFFFFFFFFu; }
}

__global__ void k_prep_cb(const float* __restrict__ cb) {
    int row = blockIdx.x, tid = threadIdx.x;
    float p = 0.0f;
    for (int d = tid; d < DIM; d += 128) {
        float v = cb[(size_t)row * DIM + d];
        g_ch[(size_t)row * DIM + d] = __float2half_rn(v);
        p = fmaf(v, v, p);
    }
#pragma unroll
    for (int off = 16; off; off >>= 1) p += __shfl_down_sync(0xffffffffu, p, off);
    __shared__ float r4[4];
    if ((tid & 31) == 0) r4[tid >> 5] = p;
    __syncthreads();
    if (tid == 0) g_c2[row] = r4[0] + r4[1] + r4[2] + r4[3];
}

__global__ void k_prep_pe() {
    int s = blockIdx.x;
    int i = threadIdx.x;
    const float c = (float)(9.210340371976184 / 512.0);
    float dvf = expf(-(float)(2 * i) * c);
    float angf = (float)s * dvf;
    float n = rintf(angf * 0.15915494309189535f);
    float rf = (float)((double)angf - (double)n * 6.283185307179586477);
    g_pe[(size_t)s * DIM + 2 * i]     = sinf(rf);
    g_pe[(size_t)s * DIM + 2 * i + 1] = cosf(rf);
}

// ---------------- launch ----------------
extern "C" void kernel_launch(void* const* d_in, const int* in_sizes, int n_in,
                              void* d_out, int out_size) {
    const float* x  = (const float*)d_in[0];
    const float* cb = (const float*)d_in[1];
    float* out = (float*)d_out;

    cudaFuncSetAttribute(k_screen, cudaFuncAttributeMaxDynamicSharedMemorySize, SMEM_DYN);

    k_prep_x<<<(NROWS * DIM / 4 + 255) / 256, 256>>>((const float4*)x);
    k_prep_cb<<<KCB, 128>>>(cb);
    k_prep_pe<<<SEQ, 256>>>();
    k_screen<<<GRIDN, 512, SMEM_DYN>>>();
    k_select<<<NROWS / 8, 256>>>(x, cb, out);
}